// round 4
// baseline (speedup 1.0000x reference)
#include <cuda_runtime.h>
#include <cstddef>

typedef unsigned long long u64;
#define Bsz 32
#define Nn  4096
#define Kk  11
#define RW  (Bsz*Kk)
#define SLOTS_ELEMS (RW*256)

__device__ __align__(16) float g_feats[(size_t)Bsz*Nn*256];
__device__ __align__(16) float g_slots[SLOTS_ELEMS];
__device__ __align__(16) float g_tmp  [SLOTS_ELEMS];
__device__ __align__(16) float g_qW   [SLOTS_ELEMS];
__device__ __align__(16) float g_updF [SLOTS_ELEMS];
__device__ __align__(16) float g_upd  [SLOTS_ELEMS];
__device__ __align__(16) float g_gi   [RW*768];
__device__ __align__(16) float g_gh   [RW*768];
__device__ __align__(16) float g_hid  [RW*1024];
__device__ __align__(16) float g_Wqk  [256*256];
__device__ __align__(16) float g_asum [RW];
__device__ __align__(16) float g_attn [(size_t)Bsz*Kk*Nn];

__device__ __forceinline__ u64 pk2(float x, float y){
    u64 r; asm("mov.b64 %0,{%1,%2};" : "=l"(r) : "f"(x), "f"(y)); return r;
}
__device__ __forceinline__ float2 upk2(u64 v){
    float2 r; asm("mov.b64 {%0,%1},%2;" : "=f"(r.x), "=f"(r.y) : "l"(v)); return r;
}
__device__ __forceinline__ u64 ffma2(u64 a, u64 b, u64 c){
    u64 d; asm("fma.rn.f32x2 %0,%1,%2,%3;" : "=l"(d) : "l"(a), "l"(b), "l"(c)); return d;
}

__global__ void slots_init_k(const float* __restrict__ z, const float* __restrict__ w,
                             const float* __restrict__ sigma){
    int i = blockIdx.x*256 + threadIdx.x;
    if (i < SLOTS_ELEMS){
        float wv = w[i % (Kk*256)];
        g_slots[i] = wv + z[i]*sigma[0]*wv;
    }
}

// LayerNorm over last dim 256, one warp per row
__global__ __launch_bounds__(256) void ln_k(const float* __restrict__ in, float* __restrict__ out,
                                            const float* __restrict__ gamma, const float* __restrict__ beta,
                                            int rows){
    int warp = threadIdx.x >> 5, lane = threadIdx.x & 31;
    int row = blockIdx.x*8 + warp;
    if (row >= rows) return;
    const float4* ip = (const float4*)(in + (size_t)row*256);
    float4 a = ip[lane], b = ip[lane+32];
    float s = a.x+a.y+a.z+a.w + b.x+b.y+b.z+b.w;
    float q = a.x*a.x+a.y*a.y+a.z*a.z+a.w*a.w + b.x*b.x+b.y*b.y+b.z*b.z+b.w*b.w;
    #pragma unroll
    for (int off=16; off; off>>=1){
        s += __shfl_xor_sync(~0u, s, off);
        q += __shfl_xor_sync(~0u, q, off);
    }
    float mean = s*(1.f/256.f);
    float var  = q*(1.f/256.f) - mean*mean;
    float rs   = rsqrtf(var + 1e-5f);
    const float4* gp = (const float4*)gamma; const float4* bp = (const float4*)beta;
    float4 g0 = gp[lane], g1 = gp[lane+32], c0 = bp[lane], c1 = bp[lane+32];
    float4* op = (float4*)(out + (size_t)row*256);
    float4 o;
    o.x=(a.x-mean)*rs*g0.x+c0.x; o.y=(a.y-mean)*rs*g0.y+c0.y;
    o.z=(a.z-mean)*rs*g0.z+c0.z; o.w=(a.w-mean)*rs*g0.w+c0.w;
    op[lane] = o;
    o.x=(b.x-mean)*rs*g1.x+c1.x; o.y=(b.y-mean)*rs*g1.y+c1.y;
    o.z=(b.z-mean)*rs*g1.z+c1.z; o.w=(b.w-mean)*rs*g1.w+c1.w;
    op[lane+32] = o;
}

// C[rows,cols] = alpha*A@B(^T) (+bias)(+relu); atomic => split-K partial atomicAdd
template<bool TRANSB>
__global__ __launch_bounds__(256) void gemm_k(const float* __restrict__ A, const float* __restrict__ B,
                                              float* __restrict__ C, const float* __restrict__ bias,
                                              int cols, int kdim, int kchunk, float alpha,
                                              int relu, int atomic){
    __shared__ __align__(16) float As[32][36];
    __shared__ __align__(16) float Bs[32][132];
    int tid  = threadIdx.x;
    int n0   = blockIdx.x*128, r0 = blockIdx.y*32, k0 = blockIdx.z*kchunk;
    int lane = tid & 31, rowg = tid >> 5;
    u64 acc01[4] = {0,0,0,0}, acc23[4] = {0,0,0,0};
    for (int kt = k0; kt < k0 + kchunk; kt += 32){
        {
            int r = tid >> 3, kg = (tid & 7) << 2;
            float4 v = *(const float4*)(A + (size_t)(r0+r)*kdim + kt + kg);
            As[r][kg]=v.x; As[r][kg+1]=v.y; As[r][kg+2]=v.z; As[r][kg+3]=v.w;
        }
        #pragma unroll
        for (int rep=0; rep<4; rep++){
            int e = rep*256 + tid;
            if (TRANSB){
                int n = e >> 3, kc = (e & 7) << 2;
                float4 v = *(const float4*)(B + (size_t)(n0+n)*kdim + kt + kc);
                Bs[kc][n]=v.x; Bs[kc+1][n]=v.y; Bs[kc+2][n]=v.z; Bs[kc+3][n]=v.w;
            } else {
                int kk = e >> 5, n4 = (e & 31) << 2;
                float4 v = *(const float4*)(B + (size_t)(kt+kk)*cols + n0 + n4);
                Bs[kk][n4]=v.x; Bs[kk][n4+1]=v.y; Bs[kk][n4+2]=v.z; Bs[kk][n4+3]=v.w;
            }
        }
        __syncthreads();
        #pragma unroll
        for (int kk=0; kk<32; kk++){
            float4 bv = *(const float4*)&Bs[kk][lane<<2];
            u64 b01 = pk2(bv.x, bv.y), b23 = pk2(bv.z, bv.w);
            #pragma unroll
            for (int r=0; r<4; r++){
                float av = As[(rowg<<2)+r][kk];
                u64 aa = pk2(av, av);
                acc01[r] = ffma2(aa, b01, acc01[r]);
                acc23[r] = ffma2(aa, b23, acc23[r]);
            }
        }
        __syncthreads();
    }
    #pragma unroll
    for (int r=0; r<4; r++){
        float2 p = upk2(acc01[r]), q = upk2(acc23[r]);
        int row = r0 + (rowg<<2) + r;
        size_t base = (size_t)row*cols + n0 + (lane<<2);
        float v0=p.x*alpha, v1=p.y*alpha, v2=q.x*alpha, v3=q.y*alpha;
        if (atomic){
            atomicAdd(&C[base+0], v0); atomicAdd(&C[base+1], v1);
            atomicAdd(&C[base+2], v2); atomicAdd(&C[base+3], v3);
        } else {
            if (bias){
                int cb = n0 + (lane<<2);
                v0+=bias[cb]; v1+=bias[cb+1]; v2+=bias[cb+2]; v3+=bias[cb+3];
            }
            if (relu){ v0=fmaxf(v0,0.f); v1=fmaxf(v1,0.f); v2=fmaxf(v2,0.f); v3=fmaxf(v3,0.f); }
            *(float4*)&C[base] = make_float4(v0,v1,v2,v3);
        }
    }
}

// logits over 11 slots, softmax over slot axis, write attn, accumulate row-sums
__global__ __launch_bounds__(256) void passA_k(float* __restrict__ attn){
    __shared__ __align__(16) float qs[Kk*256];
    int b = blockIdx.x, tid = threadIdx.x;
    for (int e = tid; e < Kk*256; e += 256) qs[e] = g_qW[b*Kk*256 + e];
    __syncthreads();
    const ulonglong2* qp = (const ulonglong2*)qs;
    float lsum[Kk];
    #pragma unroll
    for (int i=0;i<Kk;i++) lsum[i] = 0.f;
    #pragma unroll 1
    for (int j=0; j<2; j++){
        int n = blockIdx.y*512 + j*256 + tid;
        const ulonglong2* fp = (const ulonglong2*)g_feats + ((size_t)b*Nn + n)*64;
        u64 a0[Kk], a1[Kk];
        #pragma unroll
        for (int i=0;i<Kk;i++){ a0[i]=0ull; a1[i]=0ull; }
        for (int c=0; c<64; c++){
            ulonglong2 x = fp[c];
            #pragma unroll
            for (int i=0;i<Kk;i++){
                ulonglong2 w = qp[i*64 + c];
                a0[i] = ffma2(x.x, w.x, a0[i]);
                a1[i] = ffma2(x.y, w.y, a1[i]);
            }
        }
        float logit[Kk]; float m = -1e30f;
        #pragma unroll
        for (int i=0;i<Kk;i++){
            float2 p = upk2(a0[i]), q2 = upk2(a1[i]);
            logit[i] = (p.x+p.y) + (q2.x+q2.y);
            m = fmaxf(m, logit[i]);
        }
        float ssum = 0.f;
        #pragma unroll
        for (int i=0;i<Kk;i++){ logit[i] = __expf(logit[i]-m); ssum += logit[i]; }
        float inv = 1.f/ssum;
        #pragma unroll
        for (int i=0;i<Kk;i++){
            float at = logit[i]*inv;
            attn[((size_t)(b*Kk+i))*Nn + n] = at;
            lsum[i] += at;
        }
    }
    #pragma unroll
    for (int i=0;i<Kk;i++){
        float v = lsum[i];
        #pragma unroll
        for (int off=16; off; off>>=1) v += __shfl_xor_sync(~0u, v, off);
        if ((tid & 31) == 0) atomicAdd(&g_asum[b*Kk+i], v);
    }
}

// updF[b,i,f] += sum_n attn_wm[b,i,n]*feats[b,n,f]
__global__ __launch_bounds__(256) void passB_k(const float* __restrict__ attn){
    __shared__ __align__(16) float aw[Kk*1024];
    __shared__ float sinv[Kk];
    int b = blockIdx.x, ft = blockIdx.y, ns = blockIdx.z, tid = threadIdx.x;
    int n0 = ns*1024;
    if (tid < Kk) sinv[tid] = 1.f/(g_asum[b*Kk+tid] + 1e-6f);
    __syncthreads();
    for (int e = tid; e < Kk*1024; e += 256){
        int i = e >> 10, j = e & 1023;
        aw[e] = attn[((size_t)(b*Kk+i))*Nn + n0 + j] * sinv[i];
    }
    __syncthreads();
    int lane = tid & 31, warp = tid >> 5;
    u64 A0[Kk], A1[Kk];
    #pragma unroll
    for (int i=0;i<Kk;i++){ A0[i]=0ull; A1[i]=0ull; }
    const ulonglong2* fbase = (const ulonglong2*)g_feats;
    for (int n = warp; n < 1024; n += 8){
        ulonglong2 x = fbase[((size_t)b*Nn + n0 + n)*64 + ft*32 + lane];
        #pragma unroll
        for (int i=0;i<Kk;i++){
            float a = aw[(i<<10) + n];
            u64 aa = pk2(a, a);
            A0[i] = ffma2(aa, x.x, A0[i]);
            A1[i] = ffma2(aa, x.y, A1[i]);
        }
    }
    #pragma unroll
    for (int i=0;i<Kk;i++){
        float2 p = upk2(A0[i]), q = upk2(A1[i]);
        size_t base = (size_t)(b*Kk+i)*256 + ft*128 + (lane<<2);
        atomicAdd(&g_updF[base+0], p.x);
        atomicAdd(&g_updF[base+1], p.y);
        atomicAdd(&g_updF[base+2], q.x);
        atomicAdd(&g_updF[base+3], q.y);
    }
}

__global__ void gru_k(){
    int idx = blockIdx.x*256 + threadIdx.x;
    if (idx >= SLOTS_ELEMS) return;
    int row = idx >> 8, c = idx & 255;
    const float* gi = g_gi + row*768;
    const float* gh = g_gh + row*768;
    float ir = gi[c], iz = gi[256+c], in_ = gi[512+c];
    float hr = gh[c], hz = gh[256+c], hn  = gh[512+c];
    float h  = g_slots[idx];
    float r  = 1.f/(1.f + __expf(-(ir+hr)));
    float zg = 1.f/(1.f + __expf(-(iz+hz)));
    float nn = tanhf(in_ + r*hn);
    g_slots[idx] = (1.f - zg)*nn + zg*h;
}

__global__ void zero_k(float* p, int n){
    int i = blockIdx.x*256 + threadIdx.x;
    if (i < n) p[i] = 0.f;
}
__global__ void mlpadd_k(const float* __restrict__ b2){
    int i = blockIdx.x*256 + threadIdx.x;
    if (i < SLOTS_ELEMS) g_slots[i] += g_updF[i] + b2[i & 255];
}
__global__ void copy_out_k(float* __restrict__ out){
    int i = blockIdx.x*256 + threadIdx.x;
    if (i < SLOTS_ELEMS) out[i] = g_slots[i];
}

extern "C" void kernel_launch(void* const* d_in, const int* in_sizes, int n_in,
                              void* d_out, int out_size){
    const float* features=(const float*)d_in[0];
    const float* sigma=(const float*)d_in[1];
    const float* z   =(const float*)d_in[2];
    const float* w0  =(const float*)d_in[3];
    const float* gf  =(const float*)d_in[4];  const float* bf =(const float*)d_in[5];
    const float* gs  =(const float*)d_in[6];  const float* bs =(const float*)d_in[7];
    const float* gm  =(const float*)d_in[8];  const float* bm =(const float*)d_in[9];
    const float* Wk  =(const float*)d_in[10]; const float* Wv =(const float*)d_in[11];
    const float* Wq  =(const float*)d_in[12];
    const float* Wih =(const float*)d_in[13]; const float* Whh=(const float*)d_in[14];
    const float* bih =(const float*)d_in[15]; const float* bhh=(const float*)d_in[16];
    const float* W1  =(const float*)d_in[17]; const float* b1 =(const float*)d_in[18];
    const float* W2  =(const float*)d_in[19]; const float* b2 =(const float*)d_in[20];
    float* out = (float*)d_out;

    float *feats,*slots,*tmp,*qW,*updF,*upd,*gi,*gh,*hid,*Wqk,*asum,*attnbuf;
    cudaGetSymbolAddress((void**)&feats, g_feats);
    cudaGetSymbolAddress((void**)&slots, g_slots);
    cudaGetSymbolAddress((void**)&tmp,   g_tmp);
    cudaGetSymbolAddress((void**)&qW,    g_qW);
    cudaGetSymbolAddress((void**)&updF,  g_updF);
    cudaGetSymbolAddress((void**)&upd,   g_upd);
    cudaGetSymbolAddress((void**)&gi,    g_gi);
    cudaGetSymbolAddress((void**)&gh,    g_gh);
    cudaGetSymbolAddress((void**)&hid,   g_hid);
    cudaGetSymbolAddress((void**)&Wqk,   g_Wqk);
    cudaGetSymbolAddress((void**)&asum,  g_asum);
    cudaGetSymbolAddress((void**)&attnbuf, g_attn);

    slots_init_k<<<352,256>>>(z, w0, sigma);
    ln_k<<<16384,256>>>(features, feats, gf, bf, Bsz*Nn);
    gemm_k<true><<<dim3(2,8,1),256>>>(Wq, Wk, Wqk, nullptr, 256,256,256, 1.f/16.f, 0,0);

    for (int it = 0; it < 3; it++){
        float* attn = (it == 2) ? (out + SLOTS_ELEMS) : attnbuf;
        ln_k<<<44,256>>>(slots, tmp, gs, bs, RW);
        gemm_k<false><<<dim3(2,11,1),256>>>(tmp, Wqk, qW, nullptr, 256,256,256, 1.f,0,0);
        zero_k<<<2,256>>>(asum, RW);
        passA_k<<<dim3(32,8),256>>>(attn);
        zero_k<<<352,256>>>(updF, SLOTS_ELEMS);
        passB_k<<<dim3(32,2,4),256>>>(attn);
        gemm_k<false><<<dim3(2,11,1),256>>>(updF, Wv, upd, nullptr, 256,256,256, 1.f,0,0);
        gemm_k<true ><<<dim3(6,11,1),256>>>(upd,  Wih, gi, bih, 768,256,256, 1.f,0,0);
        gemm_k<true ><<<dim3(6,11,1),256>>>(slots,Whh, gh, bhh, 768,256,256, 1.f,0,0);
        gru_k<<<352,256>>>();
        ln_k<<<44,256>>>(slots, tmp, gm, bm, RW);
        gemm_k<false><<<dim3(8,11,1),256>>>(tmp, W1, hid, b1, 1024,256,256, 1.f,1,0);
        zero_k<<<352,256>>>(updF, SLOTS_ELEMS);
        gemm_k<false><<<dim3(2,11,4),256>>>(hid, W2, updF, nullptr, 256,1024,256, 1.f,0,1);
        mlpadd_k<<<352,256>>>(b2);
    }
    copy_out_k<<<352,256>>>(out);
}